// round 6
// baseline (speedup 1.0000x reference)
#include <cuda_runtime.h>

#define NMAX 200000
#define KOFF 27
#define TILE 128
#define TILESMAX ((NMAX + TILE - 1) / TILE)
#define SEGW (TILESMAX + 1)
#define BN_EPS 1e-3f

// ---------------- scratch (__device__ globals; no allocs allowed) ----------
__device__ __align__(256) float g_acc1[(size_t)NMAX * 32];
__device__ __align__(256) float g_acc2[(size_t)NMAX * 32];
__device__ int   g_seg[KOFF * SEGW];
// [0:64) L1 sum/sumsq  [64:128) L2 sum/sumsq  [128:192) L1 sc/sh  [192:256) L2 sc/sh
__device__ float g_sums[256];

// ---------------- seg: per (k, dst-tile) pair-range via binary search ------
__global__ void seg_k(const int* __restrict__ rout, int n, int tiles) {
    if (blockIdx.x == 0 && threadIdx.x < 128) g_sums[threadIdx.x] = 0.f;
    int idx = blockIdx.x * blockDim.x + threadIdx.x;
    int total = KOFF * (tiles + 1);
    if (idx >= total) return;
    int k = idx / (tiles + 1), t = idx % (tiles + 1);
    int target = t * TILE;
    if (target > n) target = n;
    const int* a = rout + (size_t)k * n;
    int lo = 0, hi = n;
    while (lo < hi) {
        int mid = (lo + hi) >> 1;
        if (a[mid] < target) lo = mid + 1; else hi = mid;
    }
    g_seg[k * SEGW + t] = lo;
}

// ---------------- conv: thread-per-pair-row, W-broadcast GEMM --------------
// Block owns 128 dst rows, 128 threads. Per offset k: packed pairs
// [seg[k][t], seg[k][t+1]); thread tx < L owns pair row tx: gathers its full
// feature row (contiguous 128B/64B), computes all 32 output cols in registers
// (A: scalar LDS, W: LDS.128 broadcast -> crossbar ~0.2x FMA), then RMWs its
// dst row in the smem C tile (dsts unique per offset => race-free).
template <int CIN, bool BNIN>
__global__ void __launch_bounds__(128) conv_k(
    const float* __restrict__ X, const float* __restrict__ W,
    const int* __restrict__ rin, const int* __restrict__ rout,
    float* __restrict__ out, int n, int statoff)
{
    const int AS = CIN + 4;               // Ash row stride (words), 16B multiple
    const int CH = CIN / 4;               // float4 per feature row

    __shared__ float C[128 * 36];
    __shared__ float Ash[128 * (CIN + 4)];
    __shared__ float Wsh[CIN * 32];
    __shared__ int   dsh[128];
    __shared__ float red[256];
    __shared__ float bns[64];
    __shared__ int   klist[KOFF], klo[KOFF], kln[KOFF], sst[KOFF], sen[KOFF];
    __shared__ int   nksh;

    int tx = threadIdx.x;
    int tile = blockIdx.x;
    int r0 = tile * TILE;

    if (BNIN && tx < 64) bns[tx] = g_sums[128 + tx];
    if (tx < KOFF) { sst[tx] = g_seg[tx * SEGW + tile]; sen[tx] = g_seg[tx * SEGW + tile + 1]; }
    #pragma unroll
    for (int i = tx; i < 128 * 9; i += 128) ((float4*)C)[i] = make_float4(0.f, 0.f, 0.f, 0.f);
    __syncthreads();
    if (tx == 0) {
        int m = 0;
        for (int k = 0; k < KOFF; k++) {
            int L = sen[k] - sst[k];
            if (L > 0) { klist[m] = k; klo[m] = sst[k]; kln[m] = L; m++; }
        }
        nksh = m;
    }
    __syncthreads();
    int nk = nksh;

    for (int j = 0; j < nk; j++) {
        int k = klist[j], s = klo[j], L = kln[j];
        __syncthreads();                  // prev compute done before restage

        // stage W_k
        const float4* Wk4 = (const float4*)(W + (size_t)k * CIN * 32);
        #pragma unroll
        for (int i = tx; i < CIN * 8; i += 128) ((float4*)Wsh)[i] = Wk4[i];

        // per-thread-row gather: rin once, contiguous feature row
        if (tx < L) {
            int src = __ldg(rin + (size_t)k * n + s + tx);
            dsh[tx] = __ldg(rout + (size_t)k * n + s + tx) - r0;
            const float4* xr = (const float4*)(X + (size_t)src * CIN);
            float* arow = &Ash[tx * AS];
            #pragma unroll
            for (int co = 0; co < CH; co++) {
                float4 v = xr[co];
                if (BNIN) {
                    float4 sc = *(const float4*)&bns[co * 4];
                    float4 sh = *(const float4*)&bns[32 + co * 4];
                    v.x = fmaxf(fmaf(v.x, sc.x, sh.x), 0.f);
                    v.y = fmaxf(fmaf(v.y, sc.y, sh.y), 0.f);
                    v.z = fmaxf(fmaf(v.z, sc.z, sh.z), 0.f);
                    v.w = fmaxf(fmaf(v.w, sc.w, sh.w), 0.f);
                }
                *(float4*)&arow[co * 4] = v;
            }
        }
        __syncthreads();

        if (tx < L) {
            float4 acc4[8];
            #pragma unroll
            for (int c = 0; c < 8; c++) acc4[c] = make_float4(0.f, 0.f, 0.f, 0.f);
            const float* arow = &Ash[tx * AS];
            #pragma unroll 4
            for (int ci = 0; ci < CIN; ci++) {
                float a = arow[ci];                     // scalar LDS, lane=row
                const float4* wrow = (const float4*)&Wsh[ci * 32];  // broadcast
                #pragma unroll
                for (int c = 0; c < 8; c++) {
                    float4 w = wrow[c];
                    acc4[c].x = fmaf(a, w.x, acc4[c].x);
                    acc4[c].y = fmaf(a, w.y, acc4[c].y);
                    acc4[c].z = fmaf(a, w.z, acc4[c].z);
                    acc4[c].w = fmaf(a, w.w, acc4[c].w);
                }
            }
            float4* crow = (float4*)&C[dsh[tx] * 36];   // unique dst: race-free
            #pragma unroll
            for (int c = 0; c < 8; c++) {
                float4 cv = crow[c];
                cv.x += acc4[c].x; cv.y += acc4[c].y;
                cv.z += acc4[c].z; cv.w += acc4[c].w;
                crow[c] = cv;
            }
        }
    }
    __syncthreads();

    // epilogue: store C tile once + fused BN statistics
    int nrows = n - r0; if (nrows > TILE) nrows = TILE;
    for (int i = tx; i < nrows * 8; i += 128) {
        int row = i >> 3, co = i & 7;
        ((float4*)(out + (size_t)(r0 + row) * 32))[co] = *(float4*)&C[row * 36 + co * 4];
    }
    int ch = tx & 31, rg = tx >> 5;       // 4 warps
    float s = 0.f, q = 0.f;
    for (int r = rg; r < nrows; r += 4) {
        float v = C[r * 36 + ch];
        s += v;
        q = fmaf(v, v, q);
    }
    red[tx] = s; red[128 + tx] = q;
    __syncthreads();
    if (tx < 32) {
        float S = 0.f, Q = 0.f;
        #pragma unroll
        for (int w = 0; w < 4; w++) { S += red[w * 32 + tx]; Q += red[128 + w * 32 + tx]; }
        atomicAdd(&g_sums[statoff + tx], S);
        atomicAdd(&g_sums[statoff + 32 + tx], Q);
    }
}

// ---------------- BN finalize ----------------------------------------------
__global__ void finalize_k(const float* __restrict__ gamma,
                           const float* __restrict__ beta,
                           int n, int off, int outoff) {
    int c = threadIdx.x;
    float inv_n = 1.f / (float)n;
    float mu  = g_sums[off + c] * inv_n;
    float var = g_sums[off + 32 + c] * inv_n - mu * mu;
    float sc  = gamma[c] * rsqrtf(var + BN_EPS);
    g_sums[outoff + c] = sc;
    g_sums[outoff + 32 + c] = beta[c] - mu * sc;
}

// ---------------- BN apply + ReLU (final output only) ----------------------
__global__ void apply_k(const float* __restrict__ in, float* __restrict__ out,
                        int n, int soff) {
    int total = n * 8;
    for (int i = blockIdx.x * blockDim.x + threadIdx.x; i < total;
         i += gridDim.x * blockDim.x) {
        int c4 = (i & 7) * 4;
        float4 v  = ((const float4*)in)[i];
        float4 sc = *(const float4*)&g_sums[soff + c4];
        float4 sh = *(const float4*)&g_sums[soff + 32 + c4];
        float4 o;
        o.x = fmaxf(fmaf(v.x, sc.x, sh.x), 0.f);
        o.y = fmaxf(fmaf(v.y, sc.y, sh.y), 0.f);
        o.z = fmaxf(fmaf(v.z, sc.z, sh.z), 0.f);
        o.w = fmaxf(fmaf(v.w, sc.w, sh.w), 0.f);
        ((float4*)out)[i] = o;
    }
}

// ---------------- launch ---------------------------------------------------
extern "C" void kernel_launch(void* const* d_in, const int* in_sizes, int n_in,
                              void* d_out, int out_size) {
    const float* feats  = (const float*)d_in[0];
    const float* W1     = (const float*)d_in[1];
    const float* gamma1 = (const float*)d_in[2];
    const float* beta1  = (const float*)d_in[3];
    const float* W2     = (const float*)d_in[4];
    const float* gamma2 = (const float*)d_in[5];
    const float* beta2  = (const float*)d_in[6];
    const int*   rin    = (const int*)d_in[7];
    const int*   rout   = (const int*)d_in[8];
    int n = in_sizes[0] / 16;

    float *acc1, *acc2;
    cudaGetSymbolAddress((void**)&acc1, g_acc1);
    cudaGetSymbolAddress((void**)&acc2, g_acc2);

    int tiles = (n + TILE - 1) / TILE;
    int segthreads = KOFF * (tiles + 1);

    seg_k<<<(segthreads + 255) / 256, 256>>>(rout, n, tiles);

    conv_k<16, false><<<tiles, 128>>>(feats, W1, rin, rout, acc1, n, 0);
    finalize_k<<<1, 32>>>(gamma1, beta1, n, 0, 128);

    conv_k<32, true><<<tiles, 128>>>(acc1, W2, rin, rout, acc2, n, 64);
    finalize_k<<<1, 32>>>(gamma2, beta2, n, 64, 192);

    apply_k<<<1184, 256>>>(acc2, (float*)d_out, n, 192);
}

// round 7
// speedup vs baseline: 1.2287x; 1.2287x over previous
#include <cuda_runtime.h>

#define NMAX 200000
#define KOFF 27
#define TILE 128
#define ASK (TILE + 4)                    // K-major A stride (words)
#define TILESMAX ((NMAX + TILE - 1) / TILE)
#define SEGW (TILESMAX + 1)
#define BN_EPS 1e-3f

// ---------------- scratch (__device__ globals; no allocs allowed) ----------
__device__ __align__(256) float g_acc1[(size_t)NMAX * 32];
__device__ __align__(256) float g_acc2[(size_t)NMAX * 32];
__device__ int   g_seg[KOFF * SEGW];
// [0:64) L1 sum/sumsq  [64:128) L2 sum/sumsq  [128:192) L1 sc/sh  [192:256) L2 sc/sh
__device__ float g_sums[256];

// ---------------- seg: per (k, dst-tile) pair-range via binary search ------
__global__ void seg_k(const int* __restrict__ rout, int n, int tiles) {
    if (blockIdx.x == 0 && threadIdx.x < 128) g_sums[threadIdx.x] = 0.f;
    int idx = blockIdx.x * blockDim.x + threadIdx.x;
    int total = KOFF * (tiles + 1);
    if (idx >= total) return;
    int k = idx / (tiles + 1), t = idx % (tiles + 1);
    int target = t * TILE;
    if (target > n) target = n;
    const int* a = rout + (size_t)k * n;
    int lo = 0, hi = n;
    while (lo < hi) {
        int mid = (lo + hi) >> 1;
        if (a[mid] < target) lo = mid + 1; else hi = mid;
    }
    g_seg[k * SEGW + t] = lo;
}

// ---------------- conv: 8x4 register tile over K-major A -------------------
// Block owns 128 dst rows, 128 threads. Per offset k: packed pair range from
// seg. Gather: thread-per-pair-row, contiguous 128B feature row -> K-major
// Ash (STS.32 bank-consecutive). GEMM: thread = 8 pair rows x 4 cols; per ci
// 3 LDS.128 (2 A broadcast-dedup + 1 W) per 32 FMA -> FMA-bound. Scatter:
// race-free RMW into smem C tile (dsts unique per offset).
template <int CIN, bool BNIN>
__global__ void __launch_bounds__(128) conv_k(
    const float* __restrict__ X, const float* __restrict__ W,
    const int* __restrict__ rin, const int* __restrict__ rout,
    float* __restrict__ out, int n, int statoff)
{
    const int CH = CIN / 4;               // float4 per feature row

    __shared__ float C[128 * 36];
    __shared__ float Ash[CIN * ASK];      // K-major: [ci][row]
    __shared__ float Wsh[CIN * 32];
    __shared__ int   dsh[128];
    __shared__ float red[256];
    __shared__ float bns[64];
    __shared__ int   klist[KOFF], klo[KOFF], kln[KOFF], sst[KOFF], sen[KOFF];
    __shared__ int   nksh;

    int tx = threadIdx.x;
    int tile = blockIdx.x;
    int r0 = tile * TILE;

    if (BNIN && tx < 64) bns[tx] = g_sums[128 + tx];
    if (tx < KOFF) { sst[tx] = g_seg[tx * SEGW + tile]; sen[tx] = g_seg[tx * SEGW + tile + 1]; }
    #pragma unroll
    for (int i = tx; i < 128 * 9; i += 128) ((float4*)C)[i] = make_float4(0.f, 0.f, 0.f, 0.f);
    __syncthreads();
    if (tx == 0) {
        int m = 0;
        for (int k = 0; k < KOFF; k++) {
            int L = sen[k] - sst[k];
            if (L > 0) { klist[m] = k; klo[m] = sst[k]; kln[m] = L; m++; }
        }
        nksh = m;
    }
    __syncthreads();
    int nk = nksh;

    const int rb = (tx >> 3) * 8;         // 16 row-groups of 8 rows
    const int cg = tx & 7;                // 8 col-groups of 4 cols

    for (int j = 0; j < nk; j++) {
        int k = klist[j], s = klo[j], L = kln[j];
        __syncthreads();                  // prev compute done before restage

        // stage W_k (row-major [ci][32])
        const float4* Wk4 = (const float4*)(W + (size_t)k * CIN * 32);
        #pragma unroll
        for (int i = tx; i < CIN * 8; i += 128) ((float4*)Wsh)[i] = Wk4[i];

        // gather: thread per pair row, contiguous feature row -> K-major Ash
        if (tx < L) {
            int src = __ldg(rin + (size_t)k * n + s + tx);
            dsh[tx] = __ldg(rout + (size_t)k * n + s + tx) - r0;
            const float4* xr = (const float4*)(X + (size_t)src * CIN);
            #pragma unroll
            for (int co = 0; co < CH; co++) {
                float4 v = xr[co];
                if (BNIN) {
                    float4 sc = *(const float4*)&bns[co * 4];
                    float4 sh = *(const float4*)&bns[32 + co * 4];
                    v.x = fmaxf(fmaf(v.x, sc.x, sh.x), 0.f);
                    v.y = fmaxf(fmaf(v.y, sc.y, sh.y), 0.f);
                    v.z = fmaxf(fmaf(v.z, sc.z, sh.z), 0.f);
                    v.w = fmaxf(fmaf(v.w, sc.w, sh.w), 0.f);
                }
                int ci = co * 4;          // STS.32 x4: lanes (=row) bank-consecutive
                Ash[(ci + 0) * ASK + tx] = v.x;
                Ash[(ci + 1) * ASK + tx] = v.y;
                Ash[(ci + 2) * ASK + tx] = v.z;
                Ash[(ci + 3) * ASK + tx] = v.w;
            }
        }
        __syncthreads();

        if (rb < L) {
            float4 cc[8];
            #pragma unroll
            for (int i = 0; i < 8; i++) cc[i] = make_float4(0.f, 0.f, 0.f, 0.f);

            #pragma unroll
            for (int ci = 0; ci < CIN; ci++) {
                float4 w  = *(const float4*)&Wsh[ci * 32 + cg * 4];
                float4 aL = *(const float4*)&Ash[ci * ASK + rb];
                float4 aH = *(const float4*)&Ash[ci * ASK + rb + 4];
                cc[0].x = fmaf(aL.x, w.x, cc[0].x); cc[0].y = fmaf(aL.x, w.y, cc[0].y);
                cc[0].z = fmaf(aL.x, w.z, cc[0].z); cc[0].w = fmaf(aL.x, w.w, cc[0].w);
                cc[1].x = fmaf(aL.y, w.x, cc[1].x); cc[1].y = fmaf(aL.y, w.y, cc[1].y);
                cc[1].z = fmaf(aL.y, w.z, cc[1].z); cc[1].w = fmaf(aL.y, w.w, cc[1].w);
                cc[2].x = fmaf(aL.z, w.x, cc[2].x); cc[2].y = fmaf(aL.z, w.y, cc[2].y);
                cc[2].z = fmaf(aL.z, w.z, cc[2].z); cc[2].w = fmaf(aL.z, w.w, cc[2].w);
                cc[3].x = fmaf(aL.w, w.x, cc[3].x); cc[3].y = fmaf(aL.w, w.y, cc[3].y);
                cc[3].z = fmaf(aL.w, w.z, cc[3].z); cc[3].w = fmaf(aL.w, w.w, cc[3].w);
                cc[4].x = fmaf(aH.x, w.x, cc[4].x); cc[4].y = fmaf(aH.x, w.y, cc[4].y);
                cc[4].z = fmaf(aH.x, w.z, cc[4].z); cc[4].w = fmaf(aH.x, w.w, cc[4].w);
                cc[5].x = fmaf(aH.y, w.x, cc[5].x); cc[5].y = fmaf(aH.y, w.y, cc[5].y);
                cc[5].z = fmaf(aH.y, w.z, cc[5].z); cc[5].w = fmaf(aH.y, w.w, cc[5].w);
                cc[6].x = fmaf(aH.z, w.x, cc[6].x); cc[6].y = fmaf(aH.z, w.y, cc[6].y);
                cc[6].z = fmaf(aH.z, w.z, cc[6].z); cc[6].w = fmaf(aH.z, w.w, cc[6].w);
                cc[7].x = fmaf(aH.w, w.x, cc[7].x); cc[7].y = fmaf(aH.w, w.y, cc[7].y);
                cc[7].z = fmaf(aH.w, w.z, cc[7].z); cc[7].w = fmaf(aH.w, w.w, cc[7].w);
            }

            #pragma unroll
            for (int i = 0; i < 8; i++) {
                int row = rb + i;
                if (row < L) {
                    float* p = &C[dsh[row] * 36 + cg * 4];   // unique dst: race-free
                    float4 cv = *(float4*)p;
                    cv.x += cc[i].x; cv.y += cc[i].y;
                    cv.z += cc[i].z; cv.w += cc[i].w;
                    *(float4*)p = cv;
                }
            }
        }
    }
    __syncthreads();

    // epilogue: store C tile once + fused BN statistics
    int nrows = n - r0; if (nrows > TILE) nrows = TILE;
    for (int i = tx; i < nrows * 8; i += 128) {
        int row = i >> 3, co = i & 7;
        ((float4*)(out + (size_t)(r0 + row) * 32))[co] = *(float4*)&C[row * 36 + co * 4];
    }
    int ch = tx & 31, wg = tx >> 5;       // 4 warps
    float s = 0.f, q = 0.f;
    for (int r = wg; r < nrows; r += 4) {
        float v = C[r * 36 + ch];
        s += v;
        q = fmaf(v, v, q);
    }
    red[tx] = s; red[128 + tx] = q;
    __syncthreads();
    if (tx < 32) {
        float S = 0.f, Q = 0.f;
        #pragma unroll
        for (int w = 0; w < 4; w++) { S += red[w * 32 + tx]; Q += red[128 + w * 32 + tx]; }
        atomicAdd(&g_sums[statoff + tx], S);
        atomicAdd(&g_sums[statoff + 32 + tx], Q);
    }
}

// ---------------- BN finalize ----------------------------------------------
__global__ void finalize_k(const float* __restrict__ gamma,
                           const float* __restrict__ beta,
                           int n, int off, int outoff) {
    int c = threadIdx.x;
    float inv_n = 1.f / (float)n;
    float mu  = g_sums[off + c] * inv_n;
    float var = g_sums[off + 32 + c] * inv_n - mu * mu;
    float sc  = gamma[c] * rsqrtf(var + BN_EPS);
    g_sums[outoff + c] = sc;
    g_sums[outoff + 32 + c] = beta[c] - mu * sc;
}

// ---------------- BN apply + ReLU (final output only) ----------------------
__global__ void apply_k(const float* __restrict__ in, float* __restrict__ out,
                        int n, int soff) {
    int total = n * 8;
    for (int i = blockIdx.x * blockDim.x + threadIdx.x; i < total;
         i += gridDim.x * blockDim.x) {
        int c4 = (i & 7) * 4;
        float4 v  = ((const float4*)in)[i];
        float4 sc = *(const float4*)&g_sums[soff + c4];
        float4 sh = *(const float4*)&g_sums[soff + 32 + c4];
        float4 o;
        o.x = fmaxf(fmaf(v.x, sc.x, sh.x), 0.f);
        o.y = fmaxf(fmaf(v.y, sc.y, sh.y), 0.f);
        o.z = fmaxf(fmaf(v.z, sc.z, sh.z), 0.f);
        o.w = fmaxf(fmaf(v.w, sc.w, sh.w), 0.f);
        ((float4*)out)[i] = o;
    }
}

// ---------------- launch ---------------------------------------------------
extern "C" void kernel_launch(void* const* d_in, const int* in_sizes, int n_in,
                              void* d_out, int out_size) {
    const float* feats  = (const float*)d_in[0];
    const float* W1     = (const float*)d_in[1];
    const float* gamma1 = (const float*)d_in[2];
    const float* beta1  = (const float*)d_in[3];
    const float* W2     = (const float*)d_in[4];
    const float* gamma2 = (const float*)d_in[5];
    const float* beta2  = (const float*)d_in[6];
    const int*   rin    = (const int*)d_in[7];
    const int*   rout   = (const int*)d_in[8];
    int n = in_sizes[0] / 16;

    float *acc1, *acc2;
    cudaGetSymbolAddress((void**)&acc1, g_acc1);
    cudaGetSymbolAddress((void**)&acc2, g_acc2);

    int tiles = (n + TILE - 1) / TILE;
    int segthreads = KOFF * (tiles + 1);

    seg_k<<<(segthreads + 255) / 256, 256>>>(rout, n, tiles);

    conv_k<16, false><<<tiles, 128>>>(feats, W1, rin, rout, acc1, n, 0);
    finalize_k<<<1, 32>>>(gamma1, beta1, n, 0, 128);

    conv_k<32, true><<<tiles, 128>>>(acc1, W2, rin, rout, acc2, n, 64);
    finalize_k<<<1, 32>>>(gamma2, beta2, n, 64, 192);

    apply_k<<<1184, 256>>>(acc2, (float*)d_out, n, 192);
}